// round 15
// baseline (speedup 1.0000x reference)
#include <cuda_runtime.h>
#include <cuda_bf16.h>
#include <math.h>
#include <stdint.h>

#define N_NODES 100000
#define N_EDGES 1600000
#define F_IN    256
#define F_HID   128
#define F_OUT   40
#define GBLK    296             // persistent graph kernel blocks (2/SM on 148 SMs)
#define NCHUNK  391             // ceil(N_NODES/256)

// ---------------- device scratch (static globals: allowed) ----------------
__device__ int   g_total;               // CSR allocation counter
__device__ volatile unsigned g_bar1, g_bar2;
__device__ unsigned g_done;
__device__ int   g_deg[N_NODES];        // zero-init; self-resets each pass
__device__ float g_dinv[N_NODES];
__device__ int   g_rowptr[N_NODES];
__device__ int   g_rend[N_NODES];
__device__ int   g_cursor[N_NODES];
__device__ int   g_ssrc[N_EDGES];       // src ids grouped by dst segment
__device__ uint32_t g_H1b[(size_t)N_NODES * 64];   // x @ W1, packed bf16x2
__device__ uint32_t g_hb [(size_t)N_NODES * 64];   // relu(agg1+b1), packed bf16x2
__device__ uint32_t g_H2b[(size_t)N_NODES * 20];   // h @ W2, packed bf16x2
// W^T baked as N-major bf16: [N][K]
__device__ __align__(16) __nv_bfloat16 g_B1hi[128 * 256];
__device__ __align__(16) __nv_bfloat16 g_B2hi[64 * 128];

// ======================= mma.sync helpers ==================================
__device__ __forceinline__ uint32_t smem_u32(const void* p) {
    uint32_t a;
    asm("{ .reg .u64 t; cvta.to.shared.u64 t, %1; cvt.u32.u64 %0, t; }"
        : "=r"(a) : "l"(p));
    return a;
}

__device__ __forceinline__ void ldsm_x4(uint32_t* r, uint32_t addr) {
    asm volatile("ldmatrix.sync.aligned.m8n8.x4.shared.b16 {%0,%1,%2,%3}, [%4];"
                 : "=r"(r[0]), "=r"(r[1]), "=r"(r[2]), "=r"(r[3]) : "r"(addr));
}

__device__ __forceinline__ void mma_bf16(float* c, const uint32_t* a, const uint32_t* b) {
    asm volatile(
        "mma.sync.aligned.m16n8k16.row.col.f32.bf16.bf16.f32 "
        "{%0,%1,%2,%3}, {%4,%5,%6,%7}, {%8,%9}, {%0,%1,%2,%3};"
        : "+f"(c[0]), "+f"(c[1]), "+f"(c[2]), "+f"(c[3])
        : "r"(a[0]), "r"(a[1]), "r"(a[2]), "r"(a[3]), "r"(b[0]), "r"(b[1]));
}

__device__ __forceinline__ uint32_t pack_bf16(float a, float b) {
    __nv_bfloat16 x = __float2bfloat16(a), y = __float2bfloat16(b);
    return ((uint32_t)__bfloat16_as_ushort(y) << 16) | __bfloat16_as_ushort(x);
}

// per-block dtype detection (first 4KB of edge_index)
__device__ __forceinline__ int detect_is64_block(const unsigned* w) {
    int loc = 0;
    for (int j = threadIdx.x; j < 512; j += blockDim.x)
        if (w[2 * j + 1] != 0u) loc = 1;
    return __syncthreads_or(loc) ? 0 : 1;
}

// software grid barrier (all GBLK blocks co-resident by launch_bounds)
__device__ __forceinline__ void grid_bar(volatile unsigned* ctr) {
    __syncthreads();
    __threadfence();
    if (threadIdx.x == 0) {
        atomicAdd((unsigned*)ctr, 1u);
        while (*ctr < (unsigned)GBLK) { }
    }
    __syncthreads();
}

// =================== GEMM1: x @ W1, single-pass bf16 =======================
__global__ __launch_bounds__(256) void k_gemm1(
    const float* __restrict__ A, int M,
    const __nv_bfloat16* __restrict__ Bhi,
    uint32_t* __restrict__ Cb)
{
    constexpr int KDIM = 256, NDIM = 128, PAD = 72, NJT = 8;
    constexpr int A_HI = 0;
    constexpr int B_HI = 128 * PAD;

    extern __shared__ __nv_bfloat16 sm[];
    const uint32_t sb = smem_u32(sm);

    const int tid  = threadIdx.x;
    const int wid  = tid >> 5;
    const int lane = tid & 31;
    const int wm = wid & 3;
    const int wn = wid >> 2;
    const int m_warp = wm * 32;
    const int n_warp = wn * 64;
    const int m0 = blockIdx.x * 128;

    float acc[2][NJT][4];
#pragma unroll
    for (int i = 0; i < 2; i++)
#pragma unroll
        for (int j = 0; j < NJT; j++)
#pragma unroll
            for (int q = 0; q < 4; q++) acc[i][j][q] = 0.f;

    const int a_off = (m_warp + (lane & 15)) * PAD + ((lane >> 4) << 3);
    const int b_off = (n_warp + (lane & 7) + ((lane >> 4) << 3)) * PAD
                    + (((lane >> 3) & 1) << 3);

    float4 areg[8];
    uint4  breg[4];
    #define LOAD_CHUNK(k0) do {                                               \
        _Pragma("unroll")                                                     \
        for (int t = 0; t < 8; t++) {                                         \
            int i = tid + t * 256;                                            \
            int m = i >> 4, q = i & 15;                                       \
            int rowg = m0 + m; if (rowg >= M) rowg = M - 1;                   \
            areg[t] = *(const float4*)(A + (size_t)rowg * KDIM + (k0) + q * 4); \
        }                                                                     \
        _Pragma("unroll")                                                     \
        for (int t = 0; t < 4; t++) {                                         \
            int i = tid + t * 256;                                            \
            int r = i >> 3, q = i & 7;                                        \
            breg[t] = *(const uint4*)(Bhi + (size_t)r * KDIM + (k0) + q * 8); \
        }                                                                     \
    } while (0)

    LOAD_CHUNK(0);

    for (int k0 = 0; k0 < KDIM; k0 += 64) {
#pragma unroll
        for (int t = 0; t < 8; t++) {
            int i = tid + t * 256;
            int m = i >> 4, q = i & 15;
            float4 v = areg[t];
            *(uint2*)(sm + A_HI + m * PAD + q * 4) =
                make_uint2(pack_bf16(v.x, v.y), pack_bf16(v.z, v.w));
        }
#pragma unroll
        for (int t = 0; t < 4; t++) {
            int i = tid + t * 256;
            int r = i >> 3, q = i & 7;
            *(uint4*)(sm + B_HI + r * PAD + q * 8) = breg[t];
        }
        __syncthreads();

        if (k0 + 64 < KDIM) LOAD_CHUNK(k0 + 64);

#pragma unroll
        for (int kk = 0; kk < 64; kk += 16) {
            uint32_t ah[2][4];
#pragma unroll
            for (int i = 0; i < 2; i++) {
                uint32_t base = (uint32_t)((a_off + i * 16 * PAD + kk) * 2);
                ldsm_x4(ah[i], sb + A_HI * 2 + base);
            }
            uint32_t bh[NJT][2];
#pragma unroll
            for (int jj = 0; jj < NJT / 2; jj++) {
                uint32_t base = (uint32_t)((b_off + jj * 16 * PAD + kk) * 2);
                uint32_t r[4];
                ldsm_x4(r, sb + B_HI * 2 + base);
                bh[2*jj][0] = r[0]; bh[2*jj][1] = r[1];
                bh[2*jj+1][0] = r[2]; bh[2*jj+1][1] = r[3];
            }
#pragma unroll
            for (int i = 0; i < 2; i++)
#pragma unroll
                for (int j = 0; j < NJT; j++)
                    mma_bf16(acc[i][j], ah[i], bh[j]);
        }
        __syncthreads();
    }
    #undef LOAD_CHUNK

#pragma unroll
    for (int i = 0; i < 2; i++) {
        int r0 = m0 + m_warp + i * 16 + (lane >> 2);
#pragma unroll
        for (int j = 0; j < NJT; j++) {
            int col = n_warp + j * 8 + (lane & 3) * 2;
            if (r0 < M)
                Cb[(size_t)r0 * 64 + (col >> 1)] = pack_bf16(acc[i][j][0], acc[i][j][1]);
            if (r0 + 8 < M)
                Cb[(size_t)(r0 + 8) * 64 + (col >> 1)] = pack_bf16(acc[i][j][2], acc[i][j][3]);
        }
    }
}

// =================== GEMM2: hb(bf16) @ W2hi, single-pass mma ===============
__global__ __launch_bounds__(256) void k_gemm2(
    const uint32_t* __restrict__ Ab, int M,
    const __nv_bfloat16* __restrict__ Bhi,
    uint32_t* __restrict__ Cb)
{
    constexpr int KDIM = 128, NDIM = 64, PAD2 = 136, NJT = 4;
    constexpr int A_HI = 0;
    constexpr int B_HI = 128 * PAD2;

    extern __shared__ __nv_bfloat16 sm[];
    const uint32_t sb = smem_u32(sm);

    const int tid  = threadIdx.x;
    const int wid  = tid >> 5;
    const int lane = tid & 31;
    const int wm = wid & 3;
    const int wn = wid >> 2;
    const int m_warp = wm * 32;
    const int n_warp = wn * 32;
    const int m0 = blockIdx.x * 128;

#pragma unroll
    for (int t = 0; t < 8; t++) {
        int i = tid + t * 256;
        int r = i >> 4, q = i & 15;
        int rowg = m0 + r; if (rowg >= M) rowg = M - 1;
        uint4 v = *(const uint4*)(Ab + (size_t)rowg * 64 + q * 4);
        *(uint4*)(sm + A_HI + r * PAD2 + q * 8) = v;
    }
#pragma unroll
    for (int t = 0; t < 4; t++) {
        int i = tid + t * 256;
        int r = i >> 4, q = i & 15;
        uint4 v = *(const uint4*)(Bhi + (size_t)r * KDIM + q * 8);
        *(uint4*)(sm + B_HI + r * PAD2 + q * 8) = v;
    }
    __syncthreads();

    float acc[2][NJT][4];
#pragma unroll
    for (int i = 0; i < 2; i++)
#pragma unroll
        for (int j = 0; j < NJT; j++)
#pragma unroll
            for (int q = 0; q < 4; q++) acc[i][j][q] = 0.f;

    const int a_off = (m_warp + (lane & 15)) * PAD2 + ((lane >> 4) << 3);
    const int b_off = (n_warp + (lane & 7) + ((lane >> 4) << 3)) * PAD2
                    + (((lane >> 3) & 1) << 3);

#pragma unroll
    for (int kk = 0; kk < KDIM; kk += 16) {
        uint32_t ah[2][4];
#pragma unroll
        for (int i = 0; i < 2; i++) {
            uint32_t base = (uint32_t)((a_off + i * 16 * PAD2 + kk) * 2);
            ldsm_x4(ah[i], sb + A_HI * 2 + base);
        }
        uint32_t bh[NJT][2];
#pragma unroll
        for (int jj = 0; jj < NJT / 2; jj++) {
            uint32_t base = (uint32_t)((b_off + jj * 16 * PAD2 + kk) * 2);
            uint32_t r[4];
            ldsm_x4(r, sb + B_HI * 2 + base);
            bh[2*jj][0] = r[0]; bh[2*jj][1] = r[1];
            bh[2*jj+1][0] = r[2]; bh[2*jj+1][1] = r[3];
        }
#pragma unroll
        for (int i = 0; i < 2; i++)
#pragma unroll
            for (int j = 0; j < NJT; j++)
                mma_bf16(acc[i][j], ah[i], bh[j]);
    }

#pragma unroll
    for (int i = 0; i < 2; i++) {
        int r0 = m0 + m_warp + i * 16 + (lane >> 2);
#pragma unroll
        for (int j = 0; j < NJT; j++) {
            int col = n_warp + j * 8 + (lane & 3) * 2;
            if (col < F_OUT) {
                if (r0 < M)
                    Cb[(size_t)r0 * 20 + (col >> 1)] = pack_bf16(acc[i][j][0], acc[i][j][1]);
                if (r0 + 8 < M)
                    Cb[(size_t)(r0 + 8) * 20 + (col >> 1)] = pack_bf16(acc[i][j][2], acc[i][j][3]);
            }
        }
    }
}

// bake BOTH W^T (N-major) bf16 images in one launch
__global__ void k_prep_both(const float* __restrict__ W1,
                            const float* __restrict__ W2,
                            __nv_bfloat16* __restrict__ hi1,
                            __nv_bfloat16* __restrict__ hi2) {
    int idx = blockIdx.x * blockDim.x + threadIdx.x;
    if (idx < 128 * 256) {
        int n = idx >> 8, k = idx & 255;
        hi1[idx] = __float2bfloat16(W1[(size_t)k * 128 + n]);
    }
    int idx2 = idx - 128 * 256;
    if (idx2 >= 0 && idx2 < 64 * 128) {
        int n = idx2 >> 7, k = idx2 & 127;
        float v = (n < F_OUT) ? W2[(size_t)k * F_OUT + n] : 0.f;
        hi2[idx2] = __float2bfloat16(v);
    }
}

// ============ persistent CSR build: deg -> alloc -> scatter ================
__global__ __launch_bounds__(256, 2) void k_graph(const void* __restrict__ ei) {
    __shared__ int sh[256];
    __shared__ int sbase;
    const int tid = threadIdx.x;
    const int gthread = blockIdx.x * 256 + tid;
    const int stride2 = GBLK * 256 * 2;
    const int is64 = detect_is64_block((const unsigned*)ei);

    // ---- phase 1: degree histogram (dst half only) ----
    for (int e2 = gthread * 2; e2 < N_EDGES; e2 += stride2) {
        int d0, d1;
        if (is64) {
            longlong2 dv = *(const longlong2*)((const long long*)ei + N_EDGES + e2);
            d0 = (int)dv.x; d1 = (int)dv.y;
        } else {
            int2 dv = *(const int2*)((const int*)ei + N_EDGES + e2);
            d0 = dv.x; d1 = dv.y;
        }
        atomicAdd(&g_deg[d0], 1);
        atomicAdd(&g_deg[d1], 1);
    }
    grid_bar(&g_bar1);

    // ---- phase 2: CSR segment allocation (block scan per 256-chunk) ----
    for (int chunk = blockIdx.x; chunk < NCHUNK; chunk += GBLK) {
        int i = chunk * 256 + tid;
        int c = (i < N_NODES) ? g_deg[i] : 0;
        if (i < N_NODES) {
            g_dinv[i] = rsqrtf((float)(c + 1));
            g_deg[i] = 0;                        // reset for next replay
        }
        sh[tid] = c;
        __syncthreads();
        for (int off = 1; off < 256; off <<= 1) {
            int t = (tid >= off) ? sh[tid - off] : 0;
            __syncthreads();
            sh[tid] += t;
            __syncthreads();
        }
        if (tid == 255) sbase = atomicAdd(&g_total, sh[255]);
        __syncthreads();
        if (i < N_NODES) {
            int beg = sbase + sh[tid] - c;
            g_rowptr[i] = beg;
            g_rend[i]   = beg + c;
            g_cursor[i] = beg;
        }
        __syncthreads();
    }
    grid_bar(&g_bar2);

    // ---- phase 3: scatter src ids into segments ----
    for (int e2 = gthread * 2; e2 < N_EDGES; e2 += stride2) {
        int s0, s1, d0, d1;
        if (is64) {
            longlong2 sv = *(const longlong2*)((const long long*)ei + e2);
            longlong2 dv = *(const longlong2*)((const long long*)ei + N_EDGES + e2);
            s0 = (int)sv.x; s1 = (int)sv.y;
            d0 = (int)dv.x; d1 = (int)dv.y;
        } else {
            int2 sv = *(const int2*)((const int*)ei + e2);
            int2 dv = *(const int2*)((const int*)ei + N_EDGES + e2);
            s0 = sv.x; s1 = sv.y;
            d0 = dv.x; d1 = dv.y;
        }
        int p0 = atomicAdd(&g_cursor[d0], 1);
        g_ssrc[p0] = s0;
        int p1 = atomicAdd(&g_cursor[d1], 1);
        g_ssrc[p1] = s1;
    }

    // ---- epilogue: last block resets barrier state for next replay ----
    __syncthreads();
    if (tid == 0) {
        __threadfence();
        unsigned d = atomicAdd(&g_done, 1u);
        if (d == (unsigned)GBLK - 1) {
            g_bar1 = 0;
            g_bar2 = 0;
            g_total = 0;
            g_done = 0;
        }
    }
}

// --------- layer-1 aggregation: warp per node, bf16 in / bf16 out ---------
__device__ __forceinline__ void acc_bf16row(float4& acc, float w, uint2 u) {
    __nv_bfloat162 p0 = *reinterpret_cast<__nv_bfloat162*>(&u.x);
    __nv_bfloat162 p1 = *reinterpret_cast<__nv_bfloat162*>(&u.y);
    acc.x += w * __low2float(p0);
    acc.y += w * __high2float(p0);
    acc.z += w * __low2float(p1);
    acc.w += w * __high2float(p1);
}

__global__ __launch_bounds__(256) void k_agg1(const float* __restrict__ b1) {
    int node = (blockIdx.x * blockDim.x + threadIdx.x) >> 5;
    if (node >= N_NODES) return;
    int lane = threadIdx.x & 31;
    float di = g_dinv[node];
    float wself = di * di;

    float4 acc = make_float4(0.f, 0.f, 0.f, 0.f);
    acc_bf16row(acc, wself, ((const uint2*)(g_H1b + (size_t)node * 64))[lane]);

    int beg = g_rowptr[node], end = g_rend[node];
    for (int p0 = beg; p0 < end; p0 += 32) {
        int myp = p0 + lane;
        int s = (myp < end) ? g_ssrc[myp] : 0;
        float ws = (myp < end) ? g_dinv[s] * di : 0.f;
        int cnt = min(32, end - p0);
        int j = 0;
        for (; j + 4 <= cnt; j += 4) {
            int   s0 = __shfl_sync(0xffffffffu, s, j);
            int   s1 = __shfl_sync(0xffffffffu, s, j + 1);
            int   s2 = __shfl_sync(0xffffffffu, s, j + 2);
            int   s3 = __shfl_sync(0xffffffffu, s, j + 3);
            float w0 = __shfl_sync(0xffffffffu, ws, j);
            float w1 = __shfl_sync(0xffffffffu, ws, j + 1);
            float w2 = __shfl_sync(0xffffffffu, ws, j + 2);
            float w3 = __shfl_sync(0xffffffffu, ws, j + 3);
            uint2 u0 = ((const uint2*)(g_H1b + (size_t)s0 * 64))[lane];
            uint2 u1 = ((const uint2*)(g_H1b + (size_t)s1 * 64))[lane];
            uint2 u2 = ((const uint2*)(g_H1b + (size_t)s2 * 64))[lane];
            uint2 u3 = ((const uint2*)(g_H1b + (size_t)s3 * 64))[lane];
            acc_bf16row(acc, w0, u0);
            acc_bf16row(acc, w1, u1);
            acc_bf16row(acc, w2, u2);
            acc_bf16row(acc, w3, u3);
        }
        for (; j < cnt; ++j) {
            int   sj = __shfl_sync(0xffffffffu, s, j);
            float wj = __shfl_sync(0xffffffffu, ws, j);
            acc_bf16row(acc, wj, ((const uint2*)(g_H1b + (size_t)sj * 64))[lane]);
        }
    }
    float4 bb = ((const float4*)b1)[lane];
    acc.x = fmaxf(acc.x + bb.x, 0.f);
    acc.y = fmaxf(acc.y + bb.y, 0.f);
    acc.z = fmaxf(acc.z + bb.z, 0.f);
    acc.w = fmaxf(acc.w + bb.w, 0.f);
    uint2 packed = make_uint2(pack_bf16(acc.x, acc.y), pack_bf16(acc.z, acc.w));
    ((uint2*)(g_hb + (size_t)node * 64))[lane] = packed;
}

// ---- layer-2 aggregation (bf16 H2 gather) + bias + log_softmax ------------
__global__ __launch_bounds__(256) void k_agg2(const float* __restrict__ b2,
                                              float* __restrict__ out) {
    int node = (blockIdx.x * blockDim.x + threadIdx.x) >> 5;
    if (node >= N_NODES) return;
    int lane = threadIdx.x & 31;
    bool act = lane < 20;
    float di = g_dinv[node];
    float wself = di * di;

    int llane = act ? lane : 0;
    float acc0 = 0.f, acc1 = 0.f;
    {
        uint32_t u = g_H2b[(size_t)node * 20 + llane];
        __nv_bfloat162 p = *reinterpret_cast<__nv_bfloat162*>(&u);
        acc0 = wself * __low2float(p);
        acc1 = wself * __high2float(p);
    }

    int beg = g_rowptr[node], end = g_rend[node];
    for (int p0 = beg; p0 < end; p0 += 32) {
        int myp = p0 + lane;
        int s = (myp < end) ? g_ssrc[myp] : 0;
        float ws = (myp < end) ? g_dinv[s] * di : 0.f;
        int cnt = min(32, end - p0);
        int j = 0;
        for (; j + 4 <= cnt; j += 4) {
            int   s0 = __shfl_sync(0xffffffffu, s, j);
            int   s1 = __shfl_sync(0xffffffffu, s, j + 1);
            int   s2 = __shfl_sync(0xffffffffu, s, j + 2);
            int   s3 = __shfl_sync(0xffffffffu, s, j + 3);
            float w0 = __shfl_sync(0xffffffffu, ws, j);
            float w1 = __shfl_sync(0xffffffffu, ws, j + 1);
            float w2 = __shfl_sync(0xffffffffu, ws, j + 2);
            float w3 = __shfl_sync(0xffffffffu, ws, j + 3);
            uint32_t u0 = g_H2b[(size_t)s0 * 20 + llane];
            uint32_t u1 = g_H2b[(size_t)s1 * 20 + llane];
            uint32_t u2 = g_H2b[(size_t)s2 * 20 + llane];
            uint32_t u3 = g_H2b[(size_t)s3 * 20 + llane];
            __nv_bfloat162 q0 = *reinterpret_cast<__nv_bfloat162*>(&u0);
            __nv_bfloat162 q1 = *reinterpret_cast<__nv_bfloat162*>(&u1);
            __nv_bfloat162 q2 = *reinterpret_cast<__nv_bfloat162*>(&u2);
            __nv_bfloat162 q3 = *reinterpret_cast<__nv_bfloat162*>(&u3);
            acc0 += w0 * __low2float(q0) + w1 * __low2float(q1)
                  + w2 * __low2float(q2) + w3 * __low2float(q3);
            acc1 += w0 * __high2float(q0) + w1 * __high2float(q1)
                  + w2 * __high2float(q2) + w3 * __high2float(q3);
        }
        for (; j < cnt; ++j) {
            int   sj = __shfl_sync(0xffffffffu, s, j);
            float wj = __shfl_sync(0xffffffffu, ws, j);
            uint32_t u = g_H2b[(size_t)sj * 20 + llane];
            __nv_bfloat162 q = *reinterpret_cast<__nv_bfloat162*>(&u);
            acc0 += wj * __low2float(q);
            acc1 += wj * __high2float(q);
        }
    }
    acc0 += b2[2 * llane];
    acc1 += b2[2 * llane + 1];

    float m = act ? fmaxf(acc0, acc1) : -1e30f;
#pragma unroll
    for (int o = 16; o; o >>= 1) m = fmaxf(m, __shfl_xor_sync(0xffffffffu, m, o));
    float e = act ? (expf(acc0 - m) + expf(acc1 - m)) : 0.f;
#pragma unroll
    for (int o = 16; o; o >>= 1) e += __shfl_xor_sync(0xffffffffu, e, o);
    float lse = m + logf(e);

    if (act) {
        float2 o2 = make_float2(acc0 - lse, acc1 - lse);
        *(float2*)(out + (size_t)node * F_OUT + 2 * lane) = o2;
    }
}

// ---------------- host launcher --------------------------------------------
extern "C" void kernel_launch(void* const* d_in, const int* in_sizes, int n_in,
                              void* d_out, int out_size) {
    const float* x  = (const float*)d_in[0];
    const void*  ei = d_in[1];
    const float* W1 = (const float*)d_in[2];
    const float* b1 = (const float*)d_in[3];
    const float* W2 = (const float*)d_in[4];
    const float* b2 = (const float*)d_in[5];
    float* out = (float*)d_out;

    uint32_t *dH1b, *dhb, *dH2b;
    __nv_bfloat16 *dB1hi, *dB2hi;
    cudaGetSymbolAddress((void**)&dH1b,  g_H1b);
    cudaGetSymbolAddress((void**)&dhb,   g_hb);
    cudaGetSymbolAddress((void**)&dH2b,  g_H2b);
    cudaGetSymbolAddress((void**)&dB1hi, g_B1hi);
    cudaGetSymbolAddress((void**)&dB2hi, g_B2hi);

    const int SMEM1 = (128 + 128) * 72 * 2;       // 36864
    const int SMEM2 = (128 + 64) * 136 * 2;       // 52224

    static cudaStream_t s2;
    static cudaEvent_t evFork, evJoin;
    static bool init_done = false;
    if (!init_done) {
        cudaFuncSetAttribute(k_gemm1,
                             cudaFuncAttributeMaxDynamicSharedMemorySize, SMEM1);
        cudaFuncSetAttribute(k_gemm2,
                             cudaFuncAttributeMaxDynamicSharedMemorySize, SMEM2);
        cudaStreamCreateWithFlags(&s2, cudaStreamNonBlocking);
        cudaEventCreateWithFlags(&evFork, cudaEventDisableTiming);
        cudaEventCreateWithFlags(&evJoin, cudaEventDisableTiming);
        init_done = true;
    }

    const int TB = 256;
    int aggBlk = (N_NODES * 32) / TB;
    int gemmBlk = (N_NODES + 127) / 128;          // 782
    int prepBlk = (128 * 256 + 64 * 128 + TB - 1) / TB;  // 160

    // ---- fork: side stream = weight bake + GEMM1; main = persistent CSR ----
    cudaEventRecord(evFork, 0);
    cudaStreamWaitEvent(s2, evFork, 0);

    k_prep_both<<<prepBlk, TB, 0, s2>>>(W1, W2, dB1hi, dB2hi);
    k_gemm1<<<gemmBlk, 256, SMEM1, s2>>>(x, N_NODES, dB1hi, dH1b);
    cudaEventRecord(evJoin, s2);

    k_graph<<<GBLK, TB>>>(ei);

    cudaStreamWaitEvent(0, evJoin, 0);

    k_agg1<<<aggBlk, TB>>>(b1);
    k_gemm2<<<gemmBlk, 256, SMEM2>>>(dhb, N_NODES, dB2hi, dH2b);
    k_agg2<<<aggBlk, TB>>>(b2, out);
}

// round 16
// speedup vs baseline: 1.2958x; 1.2958x over previous
#include <cuda_runtime.h>
#include <cuda_bf16.h>
#include <math.h>
#include <stdint.h>

#define N_NODES 100000
#define N_EDGES 1600000
#define F_IN    256
#define F_HID   128
#define F_OUT   40

// ---------------- device scratch (static globals: allowed) ----------------
__device__ int   g_is64;
__device__ int   g_total;               // CSR allocation counter (reset in k_deg)
__device__ int   g_deg[N_NODES];        // zero-init; self-resets in k_alloc
__device__ float g_dinv[N_NODES];
__device__ int   g_rowptr[N_NODES];
__device__ int   g_rend[N_NODES];
__device__ int   g_cursor[N_NODES];
__device__ int   g_ssrc[N_EDGES];       // src ids grouped by dst segment
__device__ uint32_t g_H1b[(size_t)N_NODES * 64];   // x @ W1 (scaled by dinv post k_scale)
__device__ uint32_t g_hb [(size_t)N_NODES * 64];   // dinv * relu(agg1+b1), packed bf16x2
__device__ uint32_t g_H2b[(size_t)N_NODES * 20];   // dinv-scaled h @ W2, packed bf16x2
// W^T baked as N-major bf16: [N][K]
__device__ __align__(16) __nv_bfloat16 g_B1hi[128 * 256];
__device__ __align__(16) __nv_bfloat16 g_B2hi[64 * 128];

// ======================= mma.sync helpers ==================================
__device__ __forceinline__ uint32_t smem_u32(const void* p) {
    uint32_t a;
    asm("{ .reg .u64 t; cvta.to.shared.u64 t, %1; cvt.u32.u64 %0, t; }"
        : "=r"(a) : "l"(p));
    return a;
}

__device__ __forceinline__ void ldsm_x4(uint32_t* r, uint32_t addr) {
    asm volatile("ldmatrix.sync.aligned.m8n8.x4.shared.b16 {%0,%1,%2,%3}, [%4];"
                 : "=r"(r[0]), "=r"(r[1]), "=r"(r[2]), "=r"(r[3]) : "r"(addr));
}

__device__ __forceinline__ void mma_bf16(float* c, const uint32_t* a, const uint32_t* b) {
    asm volatile(
        "mma.sync.aligned.m16n8k16.row.col.f32.bf16.bf16.f32 "
        "{%0,%1,%2,%3}, {%4,%5,%6,%7}, {%8,%9}, {%0,%1,%2,%3};"
        : "+f"(c[0]), "+f"(c[1]), "+f"(c[2]), "+f"(c[3])
        : "r"(a[0]), "r"(a[1]), "r"(a[2]), "r"(a[3]), "r"(b[0]), "r"(b[1]));
}

__device__ __forceinline__ uint32_t pack_bf16(float a, float b) {
    __nv_bfloat16 x = __float2bfloat16(a), y = __float2bfloat16(b);
    return ((uint32_t)__bfloat16_as_ushort(y) << 16) | __bfloat16_as_ushort(x);
}

// per-block dtype detection (first 4KB of edge_index)
__device__ __forceinline__ int detect_is64_block(const unsigned* w) {
    int loc = 0;
    for (int j = threadIdx.x; j < 512; j += blockDim.x)
        if (w[2 * j + 1] != 0u) loc = 1;
    return __syncthreads_or(loc) ? 0 : 1;
}

// =================== GEMM1: x @ W1, single-pass bf16 =======================
__global__ __launch_bounds__(256) void k_gemm1(
    const float* __restrict__ A, int M,
    const __nv_bfloat16* __restrict__ Bhi,
    uint32_t* __restrict__ Cb)
{
    constexpr int KDIM = 256, NDIM = 128, PAD = 72, NJT = 8;
    constexpr int A_HI = 0;
    constexpr int B_HI = 128 * PAD;

    extern __shared__ __nv_bfloat16 sm[];
    const uint32_t sb = smem_u32(sm);

    const int tid  = threadIdx.x;
    const int wid  = tid >> 5;
    const int lane = tid & 31;
    const int wm = wid & 3;
    const int wn = wid >> 2;
    const int m_warp = wm * 32;
    const int n_warp = wn * 64;
    const int m0 = blockIdx.x * 128;

    float acc[2][NJT][4];
#pragma unroll
    for (int i = 0; i < 2; i++)
#pragma unroll
        for (int j = 0; j < NJT; j++)
#pragma unroll
            for (int q = 0; q < 4; q++) acc[i][j][q] = 0.f;

    const int a_off = (m_warp + (lane & 15)) * PAD + ((lane >> 4) << 3);
    const int b_off = (n_warp + (lane & 7) + ((lane >> 4) << 3)) * PAD
                    + (((lane >> 3) & 1) << 3);

    float4 areg[8];
    uint4  breg[4];
    #define LOAD_CHUNK(k0) do {                                               \
        _Pragma("unroll")                                                     \
        for (int t = 0; t < 8; t++) {                                         \
            int i = tid + t * 256;                                            \
            int m = i >> 4, q = i & 15;                                       \
            int rowg = m0 + m; if (rowg >= M) rowg = M - 1;                   \
            areg[t] = *(const float4*)(A + (size_t)rowg * KDIM + (k0) + q * 4); \
        }                                                                     \
        _Pragma("unroll")                                                     \
        for (int t = 0; t < 4; t++) {                                         \
            int i = tid + t * 256;                                            \
            int r = i >> 3, q = i & 7;                                        \
            breg[t] = *(const uint4*)(Bhi + (size_t)r * KDIM + (k0) + q * 8); \
        }                                                                     \
    } while (0)

    LOAD_CHUNK(0);

    for (int k0 = 0; k0 < KDIM; k0 += 64) {
#pragma unroll
        for (int t = 0; t < 8; t++) {
            int i = tid + t * 256;
            int m = i >> 4, q = i & 15;
            float4 v = areg[t];
            *(uint2*)(sm + A_HI + m * PAD + q * 4) =
                make_uint2(pack_bf16(v.x, v.y), pack_bf16(v.z, v.w));
        }
#pragma unroll
        for (int t = 0; t < 4; t++) {
            int i = tid + t * 256;
            int r = i >> 3, q = i & 7;
            *(uint4*)(sm + B_HI + r * PAD + q * 8) = breg[t];
        }
        __syncthreads();

        if (k0 + 64 < KDIM) LOAD_CHUNK(k0 + 64);

#pragma unroll
        for (int kk = 0; kk < 64; kk += 16) {
            uint32_t ah[2][4];
#pragma unroll
            for (int i = 0; i < 2; i++) {
                uint32_t base = (uint32_t)((a_off + i * 16 * PAD + kk) * 2);
                ldsm_x4(ah[i], sb + A_HI * 2 + base);
            }
            uint32_t bh[NJT][2];
#pragma unroll
            for (int jj = 0; jj < NJT / 2; jj++) {
                uint32_t base = (uint32_t)((b_off + jj * 16 * PAD + kk) * 2);
                uint32_t r[4];
                ldsm_x4(r, sb + B_HI * 2 + base);
                bh[2*jj][0] = r[0]; bh[2*jj][1] = r[1];
                bh[2*jj+1][0] = r[2]; bh[2*jj+1][1] = r[3];
            }
#pragma unroll
            for (int i = 0; i < 2; i++)
#pragma unroll
                for (int j = 0; j < NJT; j++)
                    mma_bf16(acc[i][j], ah[i], bh[j]);
        }
        __syncthreads();
    }
    #undef LOAD_CHUNK

#pragma unroll
    for (int i = 0; i < 2; i++) {
        int r0 = m0 + m_warp + i * 16 + (lane >> 2);
#pragma unroll
        for (int j = 0; j < NJT; j++) {
            int col = n_warp + j * 8 + (lane & 3) * 2;
            if (r0 < M)
                Cb[(size_t)r0 * 64 + (col >> 1)] = pack_bf16(acc[i][j][0], acc[i][j][1]);
            if (r0 + 8 < M)
                Cb[(size_t)(r0 + 8) * 64 + (col >> 1)] = pack_bf16(acc[i][j][2], acc[i][j][3]);
        }
    }
}

// ====== scale H1b rows by dinv (prescale for weightless aggregation) ======
__global__ __launch_bounds__(256) void k_scale(uint32_t* __restrict__ Hb) {
    int idx = blockIdx.x * blockDim.x + threadIdx.x;   // uint2 index
    if (idx >= N_NODES * 32) return;
    int node = idx >> 5;
    float d = g_dinv[node];
    uint2 u = ((const uint2*)Hb)[idx];
    __nv_bfloat162 p0 = *reinterpret_cast<__nv_bfloat162*>(&u.x);
    __nv_bfloat162 p1 = *reinterpret_cast<__nv_bfloat162*>(&u.y);
    uint2 o;
    o.x = pack_bf16(d * __low2float(p0), d * __high2float(p0));
    o.y = pack_bf16(d * __low2float(p1), d * __high2float(p1));
    ((uint2*)Hb)[idx] = o;
}

// =================== GEMM2: hbs(bf16) @ W2hi, single-pass mma ==============
__global__ __launch_bounds__(256) void k_gemm2(
    const uint32_t* __restrict__ Ab, int M,
    const __nv_bfloat16* __restrict__ Bhi,
    uint32_t* __restrict__ Cb)
{
    constexpr int KDIM = 128, NDIM = 64, PAD2 = 136, NJT = 4;
    constexpr int A_HI = 0;
    constexpr int B_HI = 128 * PAD2;

    extern __shared__ __nv_bfloat16 sm[];
    const uint32_t sb = smem_u32(sm);

    const int tid  = threadIdx.x;
    const int wid  = tid >> 5;
    const int lane = tid & 31;
    const int wm = wid & 3;
    const int wn = wid >> 2;
    const int m_warp = wm * 32;
    const int n_warp = wn * 32;
    const int m0 = blockIdx.x * 128;

#pragma unroll
    for (int t = 0; t < 8; t++) {
        int i = tid + t * 256;
        int r = i >> 4, q = i & 15;
        int rowg = m0 + r; if (rowg >= M) rowg = M - 1;
        uint4 v = *(const uint4*)(Ab + (size_t)rowg * 64 + q * 4);
        *(uint4*)(sm + A_HI + r * PAD2 + q * 8) = v;
    }
#pragma unroll
    for (int t = 0; t < 4; t++) {
        int i = tid + t * 256;
        int r = i >> 4, q = i & 15;
        uint4 v = *(const uint4*)(Bhi + (size_t)r * KDIM + q * 8);
        *(uint4*)(sm + B_HI + r * PAD2 + q * 8) = v;
    }
    __syncthreads();

    float acc[2][NJT][4];
#pragma unroll
    for (int i = 0; i < 2; i++)
#pragma unroll
        for (int j = 0; j < NJT; j++)
#pragma unroll
            for (int q = 0; q < 4; q++) acc[i][j][q] = 0.f;

    const int a_off = (m_warp + (lane & 15)) * PAD2 + ((lane >> 4) << 3);
    const int b_off = (n_warp + (lane & 7) + ((lane >> 4) << 3)) * PAD2
                    + (((lane >> 3) & 1) << 3);

#pragma unroll
    for (int kk = 0; kk < KDIM; kk += 16) {
        uint32_t ah[2][4];
#pragma unroll
        for (int i = 0; i < 2; i++) {
            uint32_t base = (uint32_t)((a_off + i * 16 * PAD2 + kk) * 2);
            ldsm_x4(ah[i], sb + A_HI * 2 + base);
        }
        uint32_t bh[NJT][2];
#pragma unroll
        for (int jj = 0; jj < NJT / 2; jj++) {
            uint32_t base = (uint32_t)((b_off + jj * 16 * PAD2 + kk) * 2);
            uint32_t r[4];
            ldsm_x4(r, sb + B_HI * 2 + base);
            bh[2*jj][0] = r[0]; bh[2*jj][1] = r[1];
            bh[2*jj+1][0] = r[2]; bh[2*jj+1][1] = r[3];
        }
#pragma unroll
        for (int i = 0; i < 2; i++)
#pragma unroll
            for (int j = 0; j < NJT; j++)
                mma_bf16(acc[i][j], ah[i], bh[j]);
    }

#pragma unroll
    for (int i = 0; i < 2; i++) {
        int r0 = m0 + m_warp + i * 16 + (lane >> 2);
#pragma unroll
        for (int j = 0; j < NJT; j++) {
            int col = n_warp + j * 8 + (lane & 3) * 2;
            if (col < F_OUT) {
                if (r0 < M)
                    Cb[(size_t)r0 * 20 + (col >> 1)] = pack_bf16(acc[i][j][0], acc[i][j][1]);
                if (r0 + 8 < M)
                    Cb[(size_t)(r0 + 8) * 20 + (col >> 1)] = pack_bf16(acc[i][j][2], acc[i][j][3]);
            }
        }
    }
}

// bake BOTH W^T (N-major) bf16 images in one launch
__global__ void k_prep_both(const float* __restrict__ W1,
                            const float* __restrict__ W2,
                            __nv_bfloat16* __restrict__ hi1,
                            __nv_bfloat16* __restrict__ hi2) {
    int idx = blockIdx.x * blockDim.x + threadIdx.x;
    if (idx < 128 * 256) {
        int n = idx >> 8, k = idx & 255;
        hi1[idx] = __float2bfloat16(W1[(size_t)k * 128 + n]);
    }
    int idx2 = idx - 128 * 256;
    if (idx2 >= 0 && idx2 < 64 * 128) {
        int n = idx2 >> 7, k = idx2 & 127;
        float v = (n < F_OUT) ? W2[(size_t)k * F_OUT + n] : 0.f;
        hi2[idx2] = __float2bfloat16(v);
    }
}

// ---------------- preproc ---------------------------------------------------
__global__ void k_deg(const void* __restrict__ ei) {
    int is64 = detect_is64_block((const unsigned*)ei);
    if (blockIdx.x == 0 && threadIdx.x == 0) { g_total = 0; g_is64 = is64; }
    int e2 = (blockIdx.x * blockDim.x + threadIdx.x) * 2;
    if (e2 >= N_EDGES) return;
    int d0, d1;
    if (is64) {
        longlong2 dv = *(const longlong2*)((const long long*)ei + N_EDGES + e2);
        d0 = (int)dv.x; d1 = (int)dv.y;
    } else {
        int2 dv = *(const int2*)((const int*)ei + N_EDGES + e2);
        d0 = dv.x; d1 = dv.y;
    }
    atomicAdd(&g_deg[d0], 1);
    atomicAdd(&g_deg[d1], 1);
}

__global__ __launch_bounds__(256) void k_alloc() {
    __shared__ int sh[256];
    __shared__ int sbase;
    int tid = threadIdx.x;
    int i = blockIdx.x * 256 + tid;
    int c = (i < N_NODES) ? g_deg[i] : 0;
    if (i < N_NODES) {
        g_dinv[i] = rsqrtf((float)(c + 1));
        g_deg[i] = 0;
    }
    sh[tid] = c;
    __syncthreads();
    for (int off = 1; off < 256; off <<= 1) {
        int t = (tid >= off) ? sh[tid - off] : 0;
        __syncthreads();
        sh[tid] += t;
        __syncthreads();
    }
    if (tid == 255) sbase = atomicAdd(&g_total, sh[255]);
    __syncthreads();
    if (i < N_NODES) {
        int beg = sbase + sh[tid] - c;
        g_rowptr[i] = beg;
        g_rend[i]   = beg + c;
        g_cursor[i] = beg;
    }
}

__global__ void k_scatter(const void* __restrict__ ei) {
    int is64 = g_is64;
    int e2 = (blockIdx.x * blockDim.x + threadIdx.x) * 2;
    if (e2 >= N_EDGES) return;
    int s0, s1, d0, d1;
    if (is64) {
        longlong2 sv = *(const longlong2*)((const long long*)ei + e2);
        longlong2 dv = *(const longlong2*)((const long long*)ei + N_EDGES + e2);
        s0 = (int)sv.x; s1 = (int)sv.y;
        d0 = (int)dv.x; d1 = (int)dv.y;
    } else {
        int2 sv = *(const int2*)((const int*)ei + e2);
        int2 dv = *(const int2*)((const int*)ei + N_EDGES + e2);
        s0 = sv.x; s1 = sv.y;
        d0 = dv.x; d1 = dv.y;
    }
    int p0 = atomicAdd(&g_cursor[d0], 1);
    g_ssrc[p0] = s0;
    int p1 = atomicAdd(&g_cursor[d1], 1);
    g_ssrc[p1] = s1;
}

// ------ layer-1 aggregation: weightless sum of prescaled rows -------------
__device__ __forceinline__ void acc_row(float4& acc, uint2 u) {
    __nv_bfloat162 p0 = *reinterpret_cast<__nv_bfloat162*>(&u.x);
    __nv_bfloat162 p1 = *reinterpret_cast<__nv_bfloat162*>(&u.y);
    acc.x += __low2float(p0);
    acc.y += __high2float(p0);
    acc.z += __low2float(p1);
    acc.w += __high2float(p1);
}

__global__ __launch_bounds__(256) void k_agg1(const float* __restrict__ b1) {
    int node = (blockIdx.x * blockDim.x + threadIdx.x) >> 5;
    if (node >= N_NODES) return;
    int lane = threadIdx.x & 31;

    float4 acc = make_float4(0.f, 0.f, 0.f, 0.f);
    acc_row(acc, ((const uint2*)(g_H1b + (size_t)node * 64))[lane]);  // self (prescaled)

    int beg = g_rowptr[node], end = g_rend[node];
    for (int p0 = beg; p0 < end; p0 += 32) {
        int myp = p0 + lane;
        int s = (myp < end) ? g_ssrc[myp] : node;   // dup of self never read (cnt-guarded)
        int cnt = min(32, end - p0);
        int j = 0;
        for (; j + 4 <= cnt; j += 4) {
            int s0 = __shfl_sync(0xffffffffu, s, j);
            int s1 = __shfl_sync(0xffffffffu, s, j + 1);
            int s2 = __shfl_sync(0xffffffffu, s, j + 2);
            int s3 = __shfl_sync(0xffffffffu, s, j + 3);
            uint2 u0 = ((const uint2*)(g_H1b + (size_t)s0 * 64))[lane];
            uint2 u1 = ((const uint2*)(g_H1b + (size_t)s1 * 64))[lane];
            uint2 u2 = ((const uint2*)(g_H1b + (size_t)s2 * 64))[lane];
            uint2 u3 = ((const uint2*)(g_H1b + (size_t)s3 * 64))[lane];
            acc_row(acc, u0);
            acc_row(acc, u1);
            acc_row(acc, u2);
            acc_row(acc, u3);
        }
        for (; j < cnt; ++j) {
            int sj = __shfl_sync(0xffffffffu, s, j);
            acc_row(acc, ((const uint2*)(g_H1b + (size_t)sj * 64))[lane]);
        }
    }
    float di = g_dinv[node];
    float4 bb = ((const float4*)b1)[lane];
    // out = relu(di*acc + b1), then prescale by di for layer 2
    acc.x = fmaxf(di * acc.x + bb.x, 0.f) * di;
    acc.y = fmaxf(di * acc.y + bb.y, 0.f) * di;
    acc.z = fmaxf(di * acc.z + bb.z, 0.f) * di;
    acc.w = fmaxf(di * acc.w + bb.w, 0.f) * di;
    uint2 packed = make_uint2(pack_bf16(acc.x, acc.y), pack_bf16(acc.z, acc.w));
    ((uint2*)(g_hb + (size_t)node * 64))[lane] = packed;
}

// ---- layer-2 aggregation (weightless, prescaled H2s) + log_softmax --------
__global__ __launch_bounds__(256) void k_agg2(const float* __restrict__ b2,
                                              float* __restrict__ out) {
    int node = (blockIdx.x * blockDim.x + threadIdx.x) >> 5;
    if (node >= N_NODES) return;
    int lane = threadIdx.x & 31;
    bool act = lane < 20;

    int llane = act ? lane : 0;
    float acc0, acc1;
    {
        uint32_t u = g_H2b[(size_t)node * 20 + llane];
        __nv_bfloat162 p = *reinterpret_cast<__nv_bfloat162*>(&u);
        acc0 = __low2float(p);
        acc1 = __high2float(p);
    }

    int beg = g_rowptr[node], end = g_rend[node];
    for (int p0 = beg; p0 < end; p0 += 32) {
        int myp = p0 + lane;
        int s = (myp < end) ? g_ssrc[myp] : node;
        int cnt = min(32, end - p0);
        int j = 0;
        for (; j + 4 <= cnt; j += 4) {
            int s0 = __shfl_sync(0xffffffffu, s, j);
            int s1 = __shfl_sync(0xffffffffu, s, j + 1);
            int s2 = __shfl_sync(0xffffffffu, s, j + 2);
            int s3 = __shfl_sync(0xffffffffu, s, j + 3);
            uint32_t u0 = g_H2b[(size_t)s0 * 20 + llane];
            uint32_t u1 = g_H2b[(size_t)s1 * 20 + llane];
            uint32_t u2 = g_H2b[(size_t)s2 * 20 + llane];
            uint32_t u3 = g_H2b[(size_t)s3 * 20 + llane];
            __nv_bfloat162 q0 = *reinterpret_cast<__nv_bfloat162*>(&u0);
            __nv_bfloat162 q1 = *reinterpret_cast<__nv_bfloat162*>(&u1);
            __nv_bfloat162 q2 = *reinterpret_cast<__nv_bfloat162*>(&u2);
            __nv_bfloat162 q3 = *reinterpret_cast<__nv_bfloat162*>(&u3);
            acc0 += __low2float(q0) + __low2float(q1)
                  + __low2float(q2) + __low2float(q3);
            acc1 += __high2float(q0) + __high2float(q1)
                  + __high2float(q2) + __high2float(q3);
        }
        for (; j < cnt; ++j) {
            int sj = __shfl_sync(0xffffffffu, s, j);
            uint32_t u = g_H2b[(size_t)sj * 20 + llane];
            __nv_bfloat162 q = *reinterpret_cast<__nv_bfloat162*>(&u);
            acc0 += __low2float(q);
            acc1 += __high2float(q);
        }
    }
    float di = g_dinv[node];
    acc0 = di * acc0 + b2[2 * llane];
    acc1 = di * acc1 + b2[2 * llane + 1];

    float m = act ? fmaxf(acc0, acc1) : -1e30f;
#pragma unroll
    for (int o = 16; o; o >>= 1) m = fmaxf(m, __shfl_xor_sync(0xffffffffu, m, o));
    float e = act ? (expf(acc0 - m) + expf(acc1 - m)) : 0.f;
#pragma unroll
    for (int o = 16; o; o >>= 1) e += __shfl_xor_sync(0xffffffffu, e, o);
    float lse = m + logf(e);

    if (act) {
        float2 o2 = make_float2(acc0 - lse, acc1 - lse);
        *(float2*)(out + (size_t)node * F_OUT + 2 * lane) = o2;
    }
}

// ---------------- host launcher --------------------------------------------
extern "C" void kernel_launch(void* const* d_in, const int* in_sizes, int n_in,
                              void* d_out, int out_size) {
    const float* x  = (const float*)d_in[0];
    const void*  ei = d_in[1];
    const float* W1 = (const float*)d_in[2];
    const float* b1 = (const float*)d_in[3];
    const float* W2 = (const float*)d_in[4];
    const float* b2 = (const float*)d_in[5];
    float* out = (float*)d_out;

    uint32_t *dH1b, *dhb, *dH2b;
    __nv_bfloat16 *dB1hi, *dB2hi;
    cudaGetSymbolAddress((void**)&dH1b,  g_H1b);
    cudaGetSymbolAddress((void**)&dhb,   g_hb);
    cudaGetSymbolAddress((void**)&dH2b,  g_H2b);
    cudaGetSymbolAddress((void**)&dB1hi, g_B1hi);
    cudaGetSymbolAddress((void**)&dB2hi, g_B2hi);

    const int SMEM1 = (128 + 128) * 72 * 2;       // 36864
    const int SMEM2 = (128 + 64) * 136 * 2;       // 52224

    static cudaStream_t s2;
    static cudaEvent_t evFork, evAlloc, evJoin;
    static bool init_done = false;
    if (!init_done) {
        cudaFuncSetAttribute(k_gemm1,
                             cudaFuncAttributeMaxDynamicSharedMemorySize, SMEM1);
        cudaFuncSetAttribute(k_gemm2,
                             cudaFuncAttributeMaxDynamicSharedMemorySize, SMEM2);
        cudaStreamCreateWithFlags(&s2, cudaStreamNonBlocking);
        cudaEventCreateWithFlags(&evFork, cudaEventDisableTiming);
        cudaEventCreateWithFlags(&evAlloc, cudaEventDisableTiming);
        cudaEventCreateWithFlags(&evJoin, cudaEventDisableTiming);
        init_done = true;
    }

    const int TB = 256;
    int nblkN = (N_NODES + TB - 1) / TB;          // 391
    int nblkE2 = (N_EDGES / 2 + TB - 1) / TB;     // 3125
    int aggBlk = (N_NODES * 32) / TB;             // 12500
    int gemmBlk = (N_NODES + 127) / 128;          // 782
    int prepBlk = (128 * 256 + 64 * 128 + TB - 1) / TB;  // 160
    int scaleBlk = (N_NODES * 32 + TB - 1) / TB;  // 12500

    // ---- fork ----
    cudaEventRecord(evFork, 0);
    cudaStreamWaitEvent(s2, evFork, 0);

    // side stream: weights, GEMM1, then scale H1b by dinv (needs evAlloc)
    k_prep_both<<<prepBlk, TB, 0, s2>>>(W1, W2, dB1hi, dB2hi);
    k_gemm1<<<gemmBlk, 256, SMEM1, s2>>>(x, N_NODES, dB1hi, dH1b);

    // main stream: CSR build
    k_deg<<<nblkE2, TB>>>(ei);
    k_alloc<<<nblkN, TB>>>();
    cudaEventRecord(evAlloc, 0);
    k_scatter<<<nblkE2, TB>>>(ei);

    cudaStreamWaitEvent(s2, evAlloc, 0);
    k_scale<<<scaleBlk, TB, 0, s2>>>(dH1b);
    cudaEventRecord(evJoin, s2);

    cudaStreamWaitEvent(0, evJoin, 0);

    // agg1 (weightless), GEMM2 (prescaled A), agg2 (weightless) + log_softmax
    k_agg1<<<aggBlk, TB>>>(b1);
    k_gemm2<<<gemmBlk, 256, SMEM2>>>(dhb, N_NODES, dB2hi, dH2b);
    k_agg2<<<aggBlk, TB>>>(b2, out);
}

// round 17
// speedup vs baseline: 1.3271x; 1.0242x over previous
#include <cuda_runtime.h>
#include <cuda_bf16.h>
#include <math.h>
#include <stdint.h>

#define N_NODES 100000
#define N_EDGES 1600000
#define F_IN    256
#define F_HID   128
#define F_OUT   40

// ---------------- device scratch (static globals: allowed) ----------------
__device__ int   g_is64;
__device__ int   g_total;
__device__ int   g_deg[N_NODES];        // zero-init; self-resets in k_alloc
__device__ float g_dinv[N_NODES];
__device__ int   g_rowptr[N_NODES];
__device__ int   g_rend[N_NODES];
__device__ int   g_cursor[N_NODES];
__device__ int   g_ssrc[N_EDGES];
// +1 zero row (index N_NODES, never written) for unconditional gather padding
__device__ uint32_t g_H1b[(size_t)(N_NODES + 1) * 64];
__device__ uint32_t g_hb [(size_t)N_NODES * 64];
__device__ uint32_t g_H2b[(size_t)(N_NODES + 1) * 20];
__device__ __align__(16) __nv_bfloat16 g_B1hi[128 * 256];
__device__ __align__(16) __nv_bfloat16 g_B2hi[64 * 128];

// ======================= mma.sync helpers ==================================
__device__ __forceinline__ uint32_t smem_u32(const void* p) {
    uint32_t a;
    asm("{ .reg .u64 t; cvta.to.shared.u64 t, %1; cvt.u32.u64 %0, t; }"
        : "=r"(a) : "l"(p));
    return a;
}

__device__ __forceinline__ void ldsm_x4(uint32_t* r, uint32_t addr) {
    asm volatile("ldmatrix.sync.aligned.m8n8.x4.shared.b16 {%0,%1,%2,%3}, [%4];"
                 : "=r"(r[0]), "=r"(r[1]), "=r"(r[2]), "=r"(r[3]) : "r"(addr));
}

__device__ __forceinline__ void mma_bf16(float* c, const uint32_t* a, const uint32_t* b) {
    asm volatile(
        "mma.sync.aligned.m16n8k16.row.col.f32.bf16.bf16.f32 "
        "{%0,%1,%2,%3}, {%4,%5,%6,%7}, {%8,%9}, {%0,%1,%2,%3};"
        : "+f"(c[0]), "+f"(c[1]), "+f"(c[2]), "+f"(c[3])
        : "r"(a[0]), "r"(a[1]), "r"(a[2]), "r"(a[3]), "r"(b[0]), "r"(b[1]));
}

__device__ __forceinline__ uint32_t pack_bf16(float a, float b) {
    __nv_bfloat16 x = __float2bfloat16(a), y = __float2bfloat16(b);
    return ((uint32_t)__bfloat16_as_ushort(y) << 16) | __bfloat16_as_ushort(x);
}

// packed f32x2 accumulate of a bf16x2 word (bf16 -> f32 is a 16-bit shift)
__device__ __forceinline__ void acc_bf2(unsigned long long& acc, uint32_t u) {
    unsigned long long p;
    asm("mov.b64 %0, {%1,%2};" : "=l"(p) : "r"(u << 16), "r"(u & 0xffff0000u));
    asm("add.rn.f32x2 %0, %0, %1;" : "+l"(acc) : "l"(p));
}
__device__ __forceinline__ float2 unpack_x2(unsigned long long a) {
    float lo, hi;
    asm("mov.b64 {%0,%1}, %2;" : "=f"(lo), "=f"(hi) : "l"(a));
    return make_float2(lo, hi);
}

// per-block dtype detection (first 4KB of edge_index)
__device__ __forceinline__ int detect_is64_block(const unsigned* w) {
    int loc = 0;
    for (int j = threadIdx.x; j < 512; j += blockDim.x)
        if (w[2 * j + 1] != 0u) loc = 1;
    return __syncthreads_or(loc) ? 0 : 1;
}

// =================== GEMM1: x @ W1, single-pass bf16 =======================
__global__ __launch_bounds__(256) void k_gemm1(
    const float* __restrict__ A, int M,
    const __nv_bfloat16* __restrict__ Bhi,
    uint32_t* __restrict__ Cb)
{
    constexpr int KDIM = 256, NDIM = 128, PAD = 72, NJT = 8;
    constexpr int A_HI = 0;
    constexpr int B_HI = 128 * PAD;

    extern __shared__ __nv_bfloat16 sm[];
    const uint32_t sb = smem_u32(sm);

    const int tid  = threadIdx.x;
    const int wid  = tid >> 5;
    const int lane = tid & 31;
    const int wm = wid & 3;
    const int wn = wid >> 2;
    const int m_warp = wm * 32;
    const int n_warp = wn * 64;
    const int m0 = blockIdx.x * 128;

    float acc[2][NJT][4];
#pragma unroll
    for (int i = 0; i < 2; i++)
#pragma unroll
        for (int j = 0; j < NJT; j++)
#pragma unroll
            for (int q = 0; q < 4; q++) acc[i][j][q] = 0.f;

    const int a_off = (m_warp + (lane & 15)) * PAD + ((lane >> 4) << 3);
    const int b_off = (n_warp + (lane & 7) + ((lane >> 4) << 3)) * PAD
                    + (((lane >> 3) & 1) << 3);

    float4 areg[8];
    uint4  breg[4];
    #define LOAD_CHUNK(k0) do {                                               \
        _Pragma("unroll")                                                     \
        for (int t = 0; t < 8; t++) {                                         \
            int i = tid + t * 256;                                            \
            int m = i >> 4, q = i & 15;                                       \
            int rowg = m0 + m; if (rowg >= M) rowg = M - 1;                   \
            areg[t] = *(const float4*)(A + (size_t)rowg * KDIM + (k0) + q * 4); \
        }                                                                     \
        _Pragma("unroll")                                                     \
        for (int t = 0; t < 4; t++) {                                         \
            int i = tid + t * 256;                                            \
            int r = i >> 3, q = i & 7;                                        \
            breg[t] = *(const uint4*)(Bhi + (size_t)r * KDIM + (k0) + q * 8); \
        }                                                                     \
    } while (0)

    LOAD_CHUNK(0);

    for (int k0 = 0; k0 < KDIM; k0 += 64) {
#pragma unroll
        for (int t = 0; t < 8; t++) {
            int i = tid + t * 256;
            int m = i >> 4, q = i & 15;
            float4 v = areg[t];
            *(uint2*)(sm + A_HI + m * PAD + q * 4) =
                make_uint2(pack_bf16(v.x, v.y), pack_bf16(v.z, v.w));
        }
#pragma unroll
        for (int t = 0; t < 4; t++) {
            int i = tid + t * 256;
            int r = i >> 3, q = i & 7;
            *(uint4*)(sm + B_HI + r * PAD + q * 8) = breg[t];
        }
        __syncthreads();

        if (k0 + 64 < KDIM) LOAD_CHUNK(k0 + 64);

#pragma unroll
        for (int kk = 0; kk < 64; kk += 16) {
            uint32_t ah[2][4];
#pragma unroll
            for (int i = 0; i < 2; i++) {
                uint32_t base = (uint32_t)((a_off + i * 16 * PAD + kk) * 2);
                ldsm_x4(ah[i], sb + A_HI * 2 + base);
            }
            uint32_t bh[NJT][2];
#pragma unroll
            for (int jj = 0; jj < NJT / 2; jj++) {
                uint32_t base = (uint32_t)((b_off + jj * 16 * PAD + kk) * 2);
                uint32_t r[4];
                ldsm_x4(r, sb + B_HI * 2 + base);
                bh[2*jj][0] = r[0]; bh[2*jj][1] = r[1];
                bh[2*jj+1][0] = r[2]; bh[2*jj+1][1] = r[3];
            }
#pragma unroll
            for (int i = 0; i < 2; i++)
#pragma unroll
                for (int j = 0; j < NJT; j++)
                    mma_bf16(acc[i][j], ah[i], bh[j]);
        }
        __syncthreads();
    }
    #undef LOAD_CHUNK

#pragma unroll
    for (int i = 0; i < 2; i++) {
        int r0 = m0 + m_warp + i * 16 + (lane >> 2);
#pragma unroll
        for (int j = 0; j < NJT; j++) {
            int col = n_warp + j * 8 + (lane & 3) * 2;
            if (r0 < M)
                Cb[(size_t)r0 * 64 + (col >> 1)] = pack_bf16(acc[i][j][0], acc[i][j][1]);
            if (r0 + 8 < M)
                Cb[(size_t)(r0 + 8) * 64 + (col >> 1)] = pack_bf16(acc[i][j][2], acc[i][j][3]);
        }
    }
}

// ====== scale H1b rows by dinv (prescale for weightless aggregation) ======
__global__ __launch_bounds__(256) void k_scale(uint32_t* __restrict__ Hb) {
    int idx = blockIdx.x * blockDim.x + threadIdx.x;   // uint2 index
    if (idx >= N_NODES * 32) return;
    int node = idx >> 5;
    float d = g_dinv[node];
    uint2 u = ((const uint2*)Hb)[idx];
    __nv_bfloat162 p0 = *reinterpret_cast<__nv_bfloat162*>(&u.x);
    __nv_bfloat162 p1 = *reinterpret_cast<__nv_bfloat162*>(&u.y);
    uint2 o;
    o.x = pack_bf16(d * __low2float(p0), d * __high2float(p0));
    o.y = pack_bf16(d * __low2float(p1), d * __high2float(p1));
    ((uint2*)Hb)[idx] = o;
}

// =================== GEMM2: hbs(bf16) @ W2hi, single-pass mma ==============
__global__ __launch_bounds__(256) void k_gemm2(
    const uint32_t* __restrict__ Ab, int M,
    const __nv_bfloat16* __restrict__ Bhi,
    uint32_t* __restrict__ Cb)
{
    constexpr int KDIM = 128, NDIM = 64, PAD2 = 136, NJT = 4;
    constexpr int A_HI = 0;
    constexpr int B_HI = 128 * PAD2;

    extern __shared__ __nv_bfloat16 sm[];
    const uint32_t sb = smem_u32(sm);

    const int tid  = threadIdx.x;
    const int wid  = tid >> 5;
    const int lane = tid & 31;
    const int wm = wid & 3;
    const int wn = wid >> 2;
    const int m_warp = wm * 32;
    const int n_warp = wn * 32;
    const int m0 = blockIdx.x * 128;

#pragma unroll
    for (int t = 0; t < 8; t++) {
        int i = tid + t * 256;
        int r = i >> 4, q = i & 15;
        int rowg = m0 + r; if (rowg >= M) rowg = M - 1;
        uint4 v = *(const uint4*)(Ab + (size_t)rowg * 64 + q * 4);
        *(uint4*)(sm + A_HI + r * PAD2 + q * 8) = v;
    }
#pragma unroll
    for (int t = 0; t < 4; t++) {
        int i = tid + t * 256;
        int r = i >> 4, q = i & 15;
        uint4 v = *(const uint4*)(Bhi + (size_t)r * KDIM + q * 8);
        *(uint4*)(sm + B_HI + r * PAD2 + q * 8) = v;
    }
    __syncthreads();

    float acc[2][NJT][4];
#pragma unroll
    for (int i = 0; i < 2; i++)
#pragma unroll
        for (int j = 0; j < NJT; j++)
#pragma unroll
            for (int q = 0; q < 4; q++) acc[i][j][q] = 0.f;

    const int a_off = (m_warp + (lane & 15)) * PAD2 + ((lane >> 4) << 3);
    const int b_off = (n_warp + (lane & 7) + ((lane >> 4) << 3)) * PAD2
                    + (((lane >> 3) & 1) << 3);

#pragma unroll
    for (int kk = 0; kk < KDIM; kk += 16) {
        uint32_t ah[2][4];
#pragma unroll
        for (int i = 0; i < 2; i++) {
            uint32_t base = (uint32_t)((a_off + i * 16 * PAD2 + kk) * 2);
            ldsm_x4(ah[i], sb + A_HI * 2 + base);
        }
        uint32_t bh[NJT][2];
#pragma unroll
        for (int jj = 0; jj < NJT / 2; jj++) {
            uint32_t base = (uint32_t)((b_off + jj * 16 * PAD2 + kk) * 2);
            uint32_t r[4];
            ldsm_x4(r, sb + B_HI * 2 + base);
            bh[2*jj][0] = r[0]; bh[2*jj][1] = r[1];
            bh[2*jj+1][0] = r[2]; bh[2*jj+1][1] = r[3];
        }
#pragma unroll
        for (int i = 0; i < 2; i++)
#pragma unroll
            for (int j = 0; j < NJT; j++)
                mma_bf16(acc[i][j], ah[i], bh[j]);
    }

#pragma unroll
    for (int i = 0; i < 2; i++) {
        int r0 = m0 + m_warp + i * 16 + (lane >> 2);
#pragma unroll
        for (int j = 0; j < NJT; j++) {
            int col = n_warp + j * 8 + (lane & 3) * 2;
            if (col < F_OUT) {
                if (r0 < M)
                    Cb[(size_t)r0 * 20 + (col >> 1)] = pack_bf16(acc[i][j][0], acc[i][j][1]);
                if (r0 + 8 < M)
                    Cb[(size_t)(r0 + 8) * 20 + (col >> 1)] = pack_bf16(acc[i][j][2], acc[i][j][3]);
            }
        }
    }
}

// bake BOTH W^T (N-major) bf16 images in one launch
__global__ void k_prep_both(const float* __restrict__ W1,
                            const float* __restrict__ W2,
                            __nv_bfloat16* __restrict__ hi1,
                            __nv_bfloat16* __restrict__ hi2) {
    int idx = blockIdx.x * blockDim.x + threadIdx.x;
    if (idx < 128 * 256) {
        int n = idx >> 8, k = idx & 255;
        hi1[idx] = __float2bfloat16(W1[(size_t)k * 128 + n]);
    }
    int idx2 = idx - 128 * 256;
    if (idx2 >= 0 && idx2 < 64 * 128) {
        int n = idx2 >> 7, k = idx2 & 127;
        float v = (n < F_OUT) ? W2[(size_t)k * F_OUT + n] : 0.f;
        hi2[idx2] = __float2bfloat16(v);
    }
}

// ---------------- preproc ---------------------------------------------------
__global__ void k_deg(const void* __restrict__ ei) {
    int is64 = detect_is64_block((const unsigned*)ei);
    if (blockIdx.x == 0 && threadIdx.x == 0) { g_total = 0; g_is64 = is64; }
    int e2 = (blockIdx.x * blockDim.x + threadIdx.x) * 2;
    if (e2 >= N_EDGES) return;
    int d0, d1;
    if (is64) {
        longlong2 dv = *(const longlong2*)((const long long*)ei + N_EDGES + e2);
        d0 = (int)dv.x; d1 = (int)dv.y;
    } else {
        int2 dv = *(const int2*)((const int*)ei + N_EDGES + e2);
        d0 = dv.x; d1 = dv.y;
    }
    atomicAdd(&g_deg[d0], 1);
    atomicAdd(&g_deg[d1], 1);
}

__global__ __launch_bounds__(256) void k_alloc() {
    __shared__ int sh[256];
    __shared__ int sbase;
    int tid = threadIdx.x;
    int i = blockIdx.x * 256 + tid;
    int c = (i < N_NODES) ? g_deg[i] : 0;
    if (i < N_NODES) {
        g_dinv[i] = rsqrtf((float)(c + 1));
        g_deg[i] = 0;
    }
    sh[tid] = c;
    __syncthreads();
    for (int off = 1; off < 256; off <<= 1) {
        int t = (tid >= off) ? sh[tid - off] : 0;
        __syncthreads();
        sh[tid] += t;
        __syncthreads();
    }
    if (tid == 255) sbase = atomicAdd(&g_total, sh[255]);
    __syncthreads();
    if (i < N_NODES) {
        int beg = sbase + sh[tid] - c;
        g_rowptr[i] = beg;
        g_rend[i]   = beg + c;
        g_cursor[i] = beg;
    }
}

__global__ void k_scatter(const void* __restrict__ ei) {
    int is64 = g_is64;
    int e2 = (blockIdx.x * blockDim.x + threadIdx.x) * 2;
    if (e2 >= N_EDGES) return;
    int s0, s1, d0, d1;
    if (is64) {
        longlong2 sv = *(const longlong2*)((const long long*)ei + e2);
        longlong2 dv = *(const longlong2*)((const long long*)ei + N_EDGES + e2);
        s0 = (int)sv.x; s1 = (int)sv.y;
        d0 = (int)dv.x; d1 = (int)dv.y;
    } else {
        int2 sv = *(const int2*)((const int*)ei + e2);
        int2 dv = *(const int2*)((const int*)ei + N_EDGES + e2);
        s0 = sv.x; s1 = sv.y;
        d0 = dv.x; d1 = dv.y;
    }
    int p0 = atomicAdd(&g_cursor[d0], 1);
    g_ssrc[p0] = s0;
    int p1 = atomicAdd(&g_cursor[d1], 1);
    g_ssrc[p1] = s1;
}

// ------ layer-1 aggregation: 2 nodes/warp, 16-lane uint4 gathers ----------
__global__ __launch_bounds__(256) void k_agg1(const float* __restrict__ b1) {
    int gw = (blockIdx.x * blockDim.x + threadIdx.x) >> 5;   // global warp
    int lane = threadIdx.x & 31;
    int half = lane >> 4;
    int hl = lane & 15;
    int node = gw * 2 + half;                                 // N_NODES even: full warps
    if (node >= N_NODES) return;

    unsigned long long a01 = 0, a23 = 0, a45 = 0, a67 = 0;
    {
        uint4 u = ((const uint4*)(g_H1b + (size_t)node * 64))[hl];   // self (prescaled)
        acc_bf2(a01, u.x); acc_bf2(a23, u.y);
        acc_bf2(a45, u.z); acc_bf2(a67, u.w);
    }

    int beg = g_rowptr[node];
    int deg = g_rend[node] - beg;
    int dmax = max(deg, __shfl_xor_sync(0xffffffffu, deg, 16));

    for (int p0 = 0; p0 < dmax; p0 += 16) {
        int s = (p0 + hl < deg) ? g_ssrc[beg + p0 + hl] : N_NODES;  // pad -> zero row
        int cnt = min(16, dmax - p0);
        int j = 0;
        for (; j + 4 <= cnt; j += 4) {
            int s0 = __shfl_sync(0xffffffffu, s, j,     16);
            int s1 = __shfl_sync(0xffffffffu, s, j + 1, 16);
            int s2 = __shfl_sync(0xffffffffu, s, j + 2, 16);
            int s3 = __shfl_sync(0xffffffffu, s, j + 3, 16);
            uint4 u0 = ((const uint4*)(g_H1b + (size_t)s0 * 64))[hl];
            uint4 u1 = ((const uint4*)(g_H1b + (size_t)s1 * 64))[hl];
            uint4 u2 = ((const uint4*)(g_H1b + (size_t)s2 * 64))[hl];
            uint4 u3 = ((const uint4*)(g_H1b + (size_t)s3 * 64))[hl];
            acc_bf2(a01, u0.x); acc_bf2(a23, u0.y); acc_bf2(a45, u0.z); acc_bf2(a67, u0.w);
            acc_bf2(a01, u1.x); acc_bf2(a23, u1.y); acc_bf2(a45, u1.z); acc_bf2(a67, u1.w);
            acc_bf2(a01, u2.x); acc_bf2(a23, u2.y); acc_bf2(a45, u2.z); acc_bf2(a67, u2.w);
            acc_bf2(a01, u3.x); acc_bf2(a23, u3.y); acc_bf2(a45, u3.z); acc_bf2(a67, u3.w);
        }
        for (; j < cnt; ++j) {
            int sj = __shfl_sync(0xffffffffu, s, j, 16);
            uint4 u = ((const uint4*)(g_H1b + (size_t)sj * 64))[hl];
            acc_bf2(a01, u.x); acc_bf2(a23, u.y);
            acc_bf2(a45, u.z); acc_bf2(a67, u.w);
        }
    }

    float di = g_dinv[node];
    float4 bA = ((const float4*)b1)[hl * 2];
    float4 bB = ((const float4*)b1)[hl * 2 + 1];
    float2 f01 = unpack_x2(a01), f23 = unpack_x2(a23);
    float2 f45 = unpack_x2(a45), f67 = unpack_x2(a67);
    float o0 = fmaxf(di * f01.x + bA.x, 0.f) * di;
    float o1 = fmaxf(di * f01.y + bA.y, 0.f) * di;
    float o2 = fmaxf(di * f23.x + bA.z, 0.f) * di;
    float o3 = fmaxf(di * f23.y + bA.w, 0.f) * di;
    float o4 = fmaxf(di * f45.x + bB.x, 0.f) * di;
    float o5 = fmaxf(di * f45.y + bB.y, 0.f) * di;
    float o6 = fmaxf(di * f67.x + bB.z, 0.f) * di;
    float o7 = fmaxf(di * f67.y + bB.w, 0.f) * di;
    uint4 packed;
    packed.x = pack_bf16(o0, o1);
    packed.y = pack_bf16(o2, o3);
    packed.z = pack_bf16(o4, o5);
    packed.w = pack_bf16(o6, o7);
    ((uint4*)(g_hb + (size_t)node * 64))[hl] = packed;
}

// ---- layer-2 aggregation (weightless, prescaled H2s) + log_softmax --------
__global__ __launch_bounds__(256) void k_agg2(const float* __restrict__ b2,
                                              float* __restrict__ out) {
    int node = (blockIdx.x * blockDim.x + threadIdx.x) >> 5;
    if (node >= N_NODES) return;
    int lane = threadIdx.x & 31;
    bool act = lane < 20;

    int llane = act ? lane : 0;
    unsigned long long A = 0;
    acc_bf2(A, g_H2b[(size_t)node * 20 + llane]);

    int beg = g_rowptr[node], end = g_rend[node];
    for (int p0 = beg; p0 < end; p0 += 32) {
        int myp = p0 + lane;
        int s = (myp < end) ? g_ssrc[myp] : node;
        int cnt = min(32, end - p0);
        int j = 0;
        for (; j + 4 <= cnt; j += 4) {
            int s0 = __shfl_sync(0xffffffffu, s, j);
            int s1 = __shfl_sync(0xffffffffu, s, j + 1);
            int s2 = __shfl_sync(0xffffffffu, s, j + 2);
            int s3 = __shfl_sync(0xffffffffu, s, j + 3);
            uint32_t u0 = g_H2b[(size_t)s0 * 20 + llane];
            uint32_t u1 = g_H2b[(size_t)s1 * 20 + llane];
            uint32_t u2 = g_H2b[(size_t)s2 * 20 + llane];
            uint32_t u3 = g_H2b[(size_t)s3 * 20 + llane];
            acc_bf2(A, u0); acc_bf2(A, u1);
            acc_bf2(A, u2); acc_bf2(A, u3);
        }
        for (; j < cnt; ++j) {
            int sj = __shfl_sync(0xffffffffu, s, j);
            acc_bf2(A, g_H2b[(size_t)sj * 20 + llane]);
        }
    }
    float di = g_dinv[node];
    float2 f = unpack_x2(A);
    float acc0 = di * f.x + b2[2 * llane];
    float acc1 = di * f.y + b2[2 * llane + 1];

    float m = act ? fmaxf(acc0, acc1) : -1e30f;
#pragma unroll
    for (int o = 16; o; o >>= 1) m = fmaxf(m, __shfl_xor_sync(0xffffffffu, m, o));
    float e = act ? (expf(acc0 - m) + expf(acc1 - m)) : 0.f;
#pragma unroll
    for (int o = 16; o; o >>= 1) e += __shfl_xor_sync(0xffffffffu, e, o);
    float lse = m + logf(e);

    if (act) {
        float2 o2 = make_float2(acc0 - lse, acc1 - lse);
        *(float2*)(out + (size_t)node * F_OUT + 2 * lane) = o2;
    }
}

// ---------------- host launcher --------------------------------------------
extern "C" void kernel_launch(void* const* d_in, const int* in_sizes, int n_in,
                              void* d_out, int out_size) {
    const float* x  = (const float*)d_in[0];
    const void*  ei = d_in[1];
    const float* W1 = (const float*)d_in[2];
    const float* b1 = (const float*)d_in[3];
    const float* W2 = (const float*)d_in[4];
    const float* b2 = (const float*)d_in[5];
    float* out = (float*)d_out;

    uint32_t *dH1b, *dhb, *dH2b;
    __nv_bfloat16 *dB1hi, *dB2hi;
    cudaGetSymbolAddress((void**)&dH1b,  g_H1b);
    cudaGetSymbolAddress((void**)&dhb,   g_hb);
    cudaGetSymbolAddress((void**)&dH2b,  g_H2b);
    cudaGetSymbolAddress((void**)&dB1hi, g_B1hi);
    cudaGetSymbolAddress((void**)&dB2hi, g_B2hi);

    const int SMEM1 = (128 + 128) * 72 * 2;       // 36864
    const int SMEM2 = (128 + 64) * 136 * 2;       // 52224

    static cudaStream_t s2;
    static cudaEvent_t evFork, evAlloc, evJoin;
    static bool init_done = false;
    if (!init_done) {
        cudaFuncSetAttribute(k_gemm1,
                             cudaFuncAttributeMaxDynamicSharedMemorySize, SMEM1);
        cudaFuncSetAttribute(k_gemm2,
                             cudaFuncAttributeMaxDynamicSharedMemorySize, SMEM2);
        cudaStreamCreateWithFlags(&s2, cudaStreamNonBlocking);
        cudaEventCreateWithFlags(&evFork, cudaEventDisableTiming);
        cudaEventCreateWithFlags(&evAlloc, cudaEventDisableTiming);
        cudaEventCreateWithFlags(&evJoin, cudaEventDisableTiming);
        init_done = true;
    }

    const int TB = 256;
    int nblkN = (N_NODES + TB - 1) / TB;          // 391
    int nblkE2 = (N_EDGES / 2 + TB - 1) / TB;     // 3125
    int agg1Blk = (N_NODES / 2 * 32 + TB - 1) / TB;  // 6250 (2 nodes/warp)
    int agg2Blk = (N_NODES * 32) / TB;            // 12500
    int gemmBlk = (N_NODES + 127) / 128;          // 782
    int prepBlk = (128 * 256 + 64 * 128 + TB - 1) / TB;  // 160
    int scaleBlk = (N_NODES * 32 + TB - 1) / TB;  // 12500

    // ---- fork ----
    cudaEventRecord(evFork, 0);
    cudaStreamWaitEvent(s2, evFork, 0);

    k_prep_both<<<prepBlk, TB, 0, s2>>>(W1, W2, dB1hi, dB2hi);
    k_gemm1<<<gemmBlk, 256, SMEM1, s2>>>(x, N_NODES, dB1hi, dH1b);

    k_deg<<<nblkE2, TB>>>(ei);
    k_alloc<<<nblkN, TB>>>();
    cudaEventRecord(evAlloc, 0);
    k_scatter<<<nblkE2, TB>>>(ei);

    cudaStreamWaitEvent(s2, evAlloc, 0);
    k_scale<<<scaleBlk, TB, 0, s2>>>(dH1b);
    cudaEventRecord(evJoin, s2);

    cudaStreamWaitEvent(0, evJoin, 0);

    k_agg1<<<agg1Blk, TB>>>(b1);
    k_gemm2<<<gemmBlk, 256, SMEM2>>>(dhb, N_NODES, dB2hi, dH2b);
    k_agg2<<<agg2Blk, TB>>>(b2, out);
}